// round 6
// baseline (speedup 1.0000x reference)
#include <cuda_runtime.h>
#include <cuda_fp16.h>
#include <cstdint>

#define IN_F 4096
#define OUT_F 4096
#define MAX_T 8192

#define BM 128
#define BN 128
#define BK 128
#define KSTRIDE (BK + 16)     // 144B smem row stride: conflict-free lane map
#define KT (IN_F / BK)        // 32 k-tiles
#define A_STAGE (BM * KSTRIDE)            // 18432 B
#define B_STAGE (BN * KSTRIDE)            // 18432 B
#define GEMM_SMEM (2 * (A_STAGE + B_STAGE))   // 73728 B dynamic

// Scratch (device globals: allocations are banned in kernel_launch)
__device__ __align__(16) int8_t g_qx[(size_t)MAX_T * IN_F];
__device__ __align__(16) int8_t g_qw[(size_t)OUT_F * IN_F];
__device__ float g_xs[MAX_T];
__device__ int g_x_is_f32;
__device__ int g_w_is_i32;

__device__ __forceinline__ uint32_t smem_u32(const void* p) {
    uint32_t a;
    asm("{ .reg .u64 t; cvta.to.shared.u64 t, %1; cvt.u32.u64 %0, t; }"
        : "=r"(a) : "l"(p));
    return a;
}
__device__ __forceinline__ void cp16(uint32_t dst, const void* src) {
    asm volatile("cp.async.cg.shared.global [%0], [%1], 16;\n" ::"r"(dst), "l"(src));
}
#define CP_COMMIT() asm volatile("cp.async.commit_group;\n")
#define CP_WAIT(n)  asm volatile("cp.async.wait_group %0;\n" ::"n"(n))

// ---------------------------------------------------------------------------
// Kernel 0: dtype detection, parallel (harness may promote fp16->fp32,
// int8->int32). Deterministic pure function of inputs.
// ---------------------------------------------------------------------------
__global__ void detect_kernel(const void* xv, const void* wv) {
    __shared__ float sm[8];
    __shared__ int bad;
    int tid = threadIdx.x;
    if (tid == 0) bad = 0;
    __syncthreads();

    const float* xf = (const float*)xv;
    float m = 0.f;
#pragma unroll
    for (int i = 0; i < 16; i++) m = fmaxf(m, fabsf(xf[tid + 256 * i]));
#pragma unroll
    for (int o = 16; o > 0; o >>= 1) m = fmaxf(m, __shfl_xor_sync(~0u, m, o));
    int lane = tid & 31, wid = tid >> 5;
    if (lane == 0) sm[wid] = m;

    const int* wi = (const int*)wv;
    int v = wi[tid];
    if (v < -128 || v > 127) bad = 1;
    __syncthreads();

    if (tid == 0) {
        float mx = sm[0];
#pragma unroll
        for (int i = 1; i < 8; i++) mx = fmaxf(mx, sm[i]);
        g_x_is_f32 = (mx < 8.0f) ? 1 : 0;
        g_w_is_i32 = bad ? 0 : 1;
    }
}

// ---------------------------------------------------------------------------
// Kernel 1: weight repack int32 -> int8 (no-op if weight already int8)
// ---------------------------------------------------------------------------
__global__ void repack_w_kernel(const void* wv) {
    if (!g_w_is_i32) return;
    size_t idx = (size_t)blockIdx.x * blockDim.x + threadIdx.x;
    int4 v = ((const int4*)wv)[idx];
    char4 c;
    c.x = (char)v.x; c.y = (char)v.y; c.z = (char)v.z; c.w = (char)v.w;
    reinterpret_cast<char4*>(g_qw)[idx] = c;
}

// ---------------------------------------------------------------------------
// Kernel 2: per-token dynamic quantization (1 CTA / token).
// scale = max|x|/127 (fp32); q = round(x/scale) clipped — matches reference.
// ---------------------------------------------------------------------------
__global__ void quant_kernel(const void* xv, int T) {
    int t = blockIdx.x;
    if (t >= T) return;
    int tid = threadIdx.x;
    float vals[16];
    if (g_x_is_f32) {
        const float4* row = reinterpret_cast<const float4*>((const float*)xv + (size_t)t * IN_F);
#pragma unroll
        for (int i = 0; i < 4; i++) {
            float4 v = row[tid * 4 + i];
            vals[4 * i] = v.x; vals[4 * i + 1] = v.y;
            vals[4 * i + 2] = v.z; vals[4 * i + 3] = v.w;
        }
    } else {
        const float4* row = reinterpret_cast<const float4*>((const __half*)xv + (size_t)t * IN_F);
        float4 v0 = row[tid * 2], v1 = row[tid * 2 + 1];
        const __half2* h0 = (const __half2*)&v0;
        const __half2* h1 = (const __half2*)&v1;
#pragma unroll
        for (int i = 0; i < 4; i++) {
            float2 f = __half22float2(h0[i]);
            vals[2 * i] = f.x; vals[2 * i + 1] = f.y;
        }
#pragma unroll
        for (int i = 0; i < 4; i++) {
            float2 f = __half22float2(h1[i]);
            vals[8 + 2 * i] = f.x; vals[8 + 2 * i + 1] = f.y;
        }
    }
    float m = 0.f;
#pragma unroll
    for (int i = 0; i < 16; i++) m = fmaxf(m, fabsf(vals[i]));
#pragma unroll
    for (int o = 16; o > 0; o >>= 1) m = fmaxf(m, __shfl_xor_sync(~0u, m, o));
    __shared__ float sm[8];
    int lane = tid & 31, wid = tid >> 5;
    if (lane == 0) sm[wid] = m;
    __syncthreads();
    if (tid < 8) {
        float v = sm[tid];
#pragma unroll
        for (int o = 4; o > 0; o >>= 1) v = fmaxf(v, __shfl_xor_sync(0xffu, v, o));
        if (tid == 0) sm[0] = v;
    }
    __syncthreads();
    float scale = sm[0] / 127.0f;
    if (tid == 0) g_xs[t] = scale;
    int8_t q[16];
#pragma unroll
    for (int i = 0; i < 16; i++) {
        float r = rintf(__fdiv_rn(vals[i], scale));
        r = fminf(fmaxf(r, -128.f), 127.f);
        q[i] = (int8_t)(int)r;
    }
    *reinterpret_cast<int4*>(g_qx + (size_t)t * IN_F + tid * 16) =
        *reinterpret_cast<const int4*>(q);
}

// ---------------------------------------------------------------------------
// Kernel 3: int8 GEMM (q_x [T,K] @ W[N,K]^T) via mma.m16n8k32.s8.
// 2-stage cp.async, BK=128 (halves barrier count vs BK=64 at same structure).
// Fragments via direct LDS.32 at PTX-spec lane coords; stride 144 => word =
// 36*quad + (lane&3) -> banks 4q+l, all 32 distinct (conflict-free).
// 8 warps: 4(M) x 2(N); warp tile 32x64; per-warp mma grid 2x8.
// ---------------------------------------------------------------------------
__global__ void __launch_bounds__(256, 2)
gemm_kernel(const void* __restrict__ Worig, const void* __restrict__ wscv,
            const void* __restrict__ biasv, void* __restrict__ Yv, int T) {
    extern __shared__ __align__(128) int8_t dsm[];
    int8_t* sA = dsm;                  // [2][A_STAGE]
    int8_t* sB = dsm + 2 * A_STAGE;    // [2][B_STAGE]

    int tid = threadIdx.x;
    int m0 = blockIdx.y * BM;
    int n0 = blockIdx.x * BN;
    const int8_t* W = g_w_is_i32 ? g_qw : (const int8_t*)Worig;

    uint32_t aS0 = smem_u32(sA);
    uint32_t bS0 = smem_u32(sB);

    // tile loader: 128 rows x 128B per operand; thread -> (row=tid>>1,
    // 64B half=(tid&1)*64), 4 contiguous 16B chunks per operand.
    int lrow = tid >> 1;
    int lhalf = (tid & 1) * 64;
    auto load_tile = [&](int stage, int k0) {
        uint32_t ab = aS0 + stage * A_STAGE + lrow * KSTRIDE + lhalf;
        uint32_t bb = bS0 + stage * B_STAGE + lrow * KSTRIDE + lhalf;
        const int8_t* Asrc = g_qx + (size_t)(m0 + lrow) * IN_F + k0 + lhalf;
        const int8_t* Bsrc = W + (size_t)(n0 + lrow) * IN_F + k0 + lhalf;
#pragma unroll
        for (int i = 0; i < 4; i++) {
            cp16(ab + 16 * i, Asrc + 16 * i);
            cp16(bb + 16 * i, Bsrc + 16 * i);
        }
    };

    int lane = tid & 31, warp = tid >> 5;
    int wm = (warp & 3) * 32, wn = (warp >> 2) * 64;
    int quad = lane >> 2, four = (lane & 3) * 4;

    int c[2][8][4];
#pragma unroll
    for (int mt = 0; mt < 2; mt++)
#pragma unroll
        for (int nt = 0; nt < 8; nt++)
#pragma unroll
            for (int i = 0; i < 4; i++) c[mt][nt][i] = 0;

    load_tile(0, 0);
    CP_COMMIT();

    for (int kt = 0; kt < KT; ++kt) {
        if (kt + 1 < KT) {
            load_tile((kt + 1) & 1, (kt + 1) * BK);
            CP_COMMIT();
            CP_WAIT(1);
        } else {
            CP_WAIT(0);
        }
        __syncthreads();

        int st = kt & 1;
        const int8_t* pA = sA + st * A_STAGE;
        const int8_t* pB = sB + st * B_STAGE;

#pragma unroll
        for (int kk = 0; kk < BK; kk += 32) {
            int a[2][4];
#pragma unroll
            for (int mt = 0; mt < 2; ++mt) {
                const int8_t* base = pA + (wm + mt * 16 + quad) * KSTRIDE + kk + four;
                a[mt][0] = *(const int*)base;
                a[mt][1] = *(const int*)(base + 8 * KSTRIDE);
                a[mt][2] = *(const int*)(base + 16);
                a[mt][3] = *(const int*)(base + 8 * KSTRIDE + 16);
            }
            int b[8][2];
#pragma unroll
            for (int nt = 0; nt < 8; ++nt) {
                const int8_t* base = pB + (wn + nt * 8 + quad) * KSTRIDE + kk + four;
                b[nt][0] = *(const int*)base;
                b[nt][1] = *(const int*)(base + 16);
            }
#pragma unroll
            for (int mt = 0; mt < 2; ++mt)
#pragma unroll
                for (int nt = 0; nt < 8; ++nt)
                    asm volatile(
                        "mma.sync.aligned.m16n8k32.row.col.s32.s8.s8.s32 "
                        "{%0,%1,%2,%3},{%4,%5,%6,%7},{%8,%9},{%0,%1,%2,%3};\n"
                        : "+r"(c[mt][nt][0]), "+r"(c[mt][nt][1]),
                          "+r"(c[mt][nt][2]), "+r"(c[mt][nt][3])
                        : "r"(a[mt][0]), "r"(a[mt][1]), "r"(a[mt][2]), "r"(a[mt][3]),
                          "r"(b[nt][0]), "r"(b[nt][1]));
        }
        __syncthreads();
    }

    // Epilogue: y = fp16(q * ws[n] * xs[m]); y += bias[n] in fp16 (as reference)
    bool f32io = (g_x_is_f32 != 0);
#pragma unroll
    for (int mt = 0; mt < 2; ++mt) {
        int r0 = m0 + wm + mt * 16 + quad;
        float xs0 = g_xs[r0], xs1 = g_xs[r0 + 8];
#pragma unroll
        for (int nt = 0; nt < 8; ++nt) {
            int cg = n0 + wn + nt * 8 + (lane & 3) * 2;
            float w0, w1;
            __half b0, b1;
            if (f32io) {
                w0 = ((const float*)wscv)[cg]; w1 = ((const float*)wscv)[cg + 1];
                b0 = __float2half(((const float*)biasv)[cg]);   // exact (orig fp16)
                b1 = __float2half(((const float*)biasv)[cg + 1]);
            } else {
                w0 = __half2float(((const __half*)wscv)[cg]);
                w1 = __half2float(((const __half*)wscv)[cg + 1]);
                b0 = ((const __half*)biasv)[cg];
                b1 = ((const __half*)biasv)[cg + 1];
            }
            __half y00 = __hadd(__float2half((float)c[mt][nt][0] * w0 * xs0), b0);
            __half y01 = __hadd(__float2half((float)c[mt][nt][1] * w1 * xs0), b1);
            __half y10 = __hadd(__float2half((float)c[mt][nt][2] * w0 * xs1), b0);
            __half y11 = __hadd(__float2half((float)c[mt][nt][3] * w1 * xs1), b1);
            if (f32io) {
                float* Y = (float*)Yv;
                if (r0 < T) *reinterpret_cast<float2*>(Y + (size_t)r0 * OUT_F + cg) =
                    make_float2(__half2float(y00), __half2float(y01));
                if (r0 + 8 < T) *reinterpret_cast<float2*>(Y + (size_t)(r0 + 8) * OUT_F + cg) =
                    make_float2(__half2float(y10), __half2float(y11));
            } else {
                __half* Y = (__half*)Yv;
                if (r0 < T) { __half2 o; o.x = y00; o.y = y01;
                    *reinterpret_cast<__half2*>(Y + (size_t)r0 * OUT_F + cg) = o; }
                if (r0 + 8 < T) { __half2 o; o.x = y10; o.y = y11;
                    *reinterpret_cast<__half2*>(Y + (size_t)(r0 + 8) * OUT_F + cg) = o; }
            }
        }
    }
}

// ---------------------------------------------------------------------------
extern "C" void kernel_launch(void* const* d_in, const int* in_sizes, int n_in,
                              void* d_out, int out_size) {
    const void* x    = d_in[0];
    const void* w    = d_in[1];
    const void* wsc  = d_in[2];
    const void* bias = d_in[3];
    int T = in_sizes[0] / IN_F;

    cudaFuncSetAttribute(gemm_kernel,
        cudaFuncAttributeMaxDynamicSharedMemorySize, GEMM_SMEM);

    detect_kernel<<<1, 256>>>(x, w);
    repack_w_kernel<<<(OUT_F * IN_F / 4) / 256, 256>>>(w);
    quant_kernel<<<T, 256>>>(x, T);

    dim3 grid(OUT_F / BN, (T + BM - 1) / BM);
    gemm_kernel<<<grid, 256, GEMM_SMEM>>>(w, wsc, bias, d_out, T);
}

// round 7
// speedup vs baseline: 1.0861x; 1.0861x over previous
#include <cuda_runtime.h>
#include <cuda_fp16.h>
#include <cstdint>

#define IN_F 4096
#define OUT_F 4096
#define MAX_T 8192

#define BM 128
#define BN 128
#define BK 64
#define KSTRIDE (BK + 16)     // 80-byte smem row stride: conflict-free lane map
#define KT (IN_F / BK)        // 64 k-tiles

// Scratch (device globals: allocations are banned in kernel_launch)
__device__ __align__(16) int8_t g_qx[(size_t)MAX_T * IN_F];
__device__ __align__(16) int8_t g_qw[(size_t)OUT_F * IN_F];
__device__ float g_xs[MAX_T];
__device__ int g_x_is_f32;
__device__ int g_w_is_i32;

__device__ __forceinline__ void cp16(uint32_t dst, const void* src) {
    asm volatile("cp.async.cg.shared.global [%0], [%1], 16;\n" ::"r"(dst), "l"(src));
}

// ---------------------------------------------------------------------------
// Kernel 0: dtype detection, parallel (harness may promote fp16->fp32,
// int8->int32). Deterministic pure function of the inputs.
// ---------------------------------------------------------------------------
__global__ void detect_kernel(const void* xv, const void* wv) {
    __shared__ float sm[8];
    __shared__ int bad;
    int tid = threadIdx.x;
    if (tid == 0) bad = 0;
    __syncthreads();

    // x: max |fp32| over first 4096 slots. true fp32 N(0,1) -> < 8;
    // fp16-pair misread as fp32 -> astronomically large w.p. ~1.
    const float* xf = (const float*)xv;
    float m = 0.f;
#pragma unroll
    for (int i = 0; i < 16; i++) m = fmaxf(m, fabsf(xf[tid + 256 * i]));
#pragma unroll
    for (int o = 16; o > 0; o >>= 1) m = fmaxf(m, __shfl_xor_sync(~0u, m, o));
    int lane = tid & 31, wid = tid >> 5;
    if (lane == 0) sm[wid] = m;

    // weight: int32 view of first 256 slots all in [-128,127] <=> promoted int8
    const int* wi = (const int*)wv;
    int v = wi[tid];
    if (v < -128 || v > 127) bad = 1;
    __syncthreads();

    if (tid == 0) {
        float mx = sm[0];
#pragma unroll
        for (int i = 1; i < 8; i++) mx = fmaxf(mx, sm[i]);
        g_x_is_f32 = (mx < 8.0f) ? 1 : 0;
        g_w_is_i32 = bad ? 0 : 1;
    }
}

// ---------------------------------------------------------------------------
// Kernel 1: weight repack int32 -> int8 (no-op if weight already int8)
// ---------------------------------------------------------------------------
__global__ void repack_w_kernel(const void* wv) {
    if (!g_w_is_i32) return;
    size_t idx = (size_t)blockIdx.x * blockDim.x + threadIdx.x;
    int4 v = ((const int4*)wv)[idx];
    char4 c;
    c.x = (char)v.x; c.y = (char)v.y; c.z = (char)v.z; c.w = (char)v.w;
    reinterpret_cast<char4*>(g_qw)[idx] = c;
}

// ---------------------------------------------------------------------------
// Kernel 2: per-token dynamic quantization (1 CTA / token).
// scale = max|x|/127 (fp32); q = round(x/scale) clipped — matches reference.
// ---------------------------------------------------------------------------
__global__ void quant_kernel(const void* xv, int T) {
    int t = blockIdx.x;
    if (t >= T) return;
    int tid = threadIdx.x;
    float vals[16];
    if (g_x_is_f32) {
        const float4* row = reinterpret_cast<const float4*>((const float*)xv + (size_t)t * IN_F);
#pragma unroll
        for (int i = 0; i < 4; i++) {
            float4 v = row[tid * 4 + i];
            vals[4 * i] = v.x; vals[4 * i + 1] = v.y;
            vals[4 * i + 2] = v.z; vals[4 * i + 3] = v.w;
        }
    } else {
        const float4* row = reinterpret_cast<const float4*>((const __half*)xv + (size_t)t * IN_F);
        float4 v0 = row[tid * 2], v1 = row[tid * 2 + 1];
        const __half2* h0 = (const __half2*)&v0;
        const __half2* h1 = (const __half2*)&v1;
#pragma unroll
        for (int i = 0; i < 4; i++) {
            float2 f = __half22float2(h0[i]);
            vals[2 * i] = f.x; vals[2 * i + 1] = f.y;
        }
#pragma unroll
        for (int i = 0; i < 4; i++) {
            float2 f = __half22float2(h1[i]);
            vals[8 + 2 * i] = f.x; vals[8 + 2 * i + 1] = f.y;
        }
    }
    float m = 0.f;
#pragma unroll
    for (int i = 0; i < 16; i++) m = fmaxf(m, fabsf(vals[i]));
#pragma unroll
    for (int o = 16; o > 0; o >>= 1) m = fmaxf(m, __shfl_xor_sync(~0u, m, o));
    __shared__ float sm[8];
    int lane = tid & 31, wid = tid >> 5;
    if (lane == 0) sm[wid] = m;
    __syncthreads();
    if (tid < 8) {
        float v = sm[tid];
#pragma unroll
        for (int o = 4; o > 0; o >>= 1) v = fmaxf(v, __shfl_xor_sync(0xffu, v, o));
        if (tid == 0) sm[0] = v;
    }
    __syncthreads();
    float scale = sm[0] / 127.0f;
    if (tid == 0) g_xs[t] = scale;
    int8_t q[16];
#pragma unroll
    for (int i = 0; i < 16; i++) {
        float r = rintf(__fdiv_rn(vals[i], scale));
        r = fminf(fmaxf(r, -128.f), 127.f);
        q[i] = (int8_t)(int)r;
    }
    *reinterpret_cast<int4*>(g_qx + (size_t)t * IN_F + tid * 16) =
        *reinterpret_cast<const int4*>(q);
}

// ---------------------------------------------------------------------------
// Kernel 3: int8 GEMM — EXACT R3 configuration (measured 91.5% tensor pipe).
// mma.m16n8k32.s8, 2-stage cp.async, static smem, BK=64, two syncs/iter.
// Fragments via direct LDS.32 at PTX-spec lane coords (conflict-free,
// KSTRIDE=80: word idx = 20*(lane>>2)+(lane&3) covers all 32 banks once).
// 8 warps: 4(M) x 2(N); warp tile 32x64; per-warp mma grid 2x8.
// ---------------------------------------------------------------------------
__global__ void __launch_bounds__(256, 2)
gemm_kernel(const void* Worig, const void* wscv, const void* biasv,
            void* Yv, int T) {
    __shared__ __align__(128) int8_t sA[2][BM * KSTRIDE];
    __shared__ __align__(128) int8_t sB[2][BN * KSTRIDE];

    int tid = threadIdx.x;
    int m0 = blockIdx.y * BM;
    int n0 = blockIdx.x * BN;
    const int8_t* W = g_w_is_i32 ? g_qw : (const int8_t*)Worig;

    auto load_tile = [&](int stage, int k0) {
        uint32_t abase = (uint32_t)__cvta_generic_to_shared(sA[stage]);
        uint32_t bbase = (uint32_t)__cvta_generic_to_shared(sB[stage]);
#pragma unroll
        for (int i = 0; i < 2; i++) {
            int c = tid + i * 256;
            int r = c >> 2, p = (c & 3) * 16;
            cp16(abase + r * KSTRIDE + p, g_qx + (size_t)(m0 + r) * IN_F + k0 + p);
            cp16(bbase + r * KSTRIDE + p, W + (size_t)(n0 + r) * IN_F + k0 + p);
        }
    };

    int lane = tid & 31;
    int warp = tid >> 5;
    int wm = (warp & 3) * 32;
    int wn = (warp >> 2) * 64;
    int quad = lane >> 2;
    int four = (lane & 3) * 4;

    int c[2][8][4];
#pragma unroll
    for (int mt = 0; mt < 2; mt++)
#pragma unroll
        for (int nt = 0; nt < 8; nt++)
#pragma unroll
            for (int i = 0; i < 4; i++) c[mt][nt][i] = 0;

    load_tile(0, 0);
    asm volatile("cp.async.commit_group;\n");

    for (int kt = 0; kt < KT; ++kt) {
        if (kt + 1 < KT) {
            load_tile((kt + 1) & 1, (kt + 1) * BK);
            asm volatile("cp.async.commit_group;\n");
            asm volatile("cp.async.wait_group 1;\n");
        } else {
            asm volatile("cp.async.wait_group 0;\n");
        }
        __syncthreads();

        int st = kt & 1;
        const int8_t* pA = sA[st];
        const int8_t* pB = sB[st];

#pragma unroll
        for (int kk = 0; kk < BK; kk += 32) {
            int a[2][4];
#pragma unroll
            for (int mt = 0; mt < 2; ++mt) {
                const int8_t* base = pA + (wm + mt * 16 + quad) * KSTRIDE + kk + four;
                a[mt][0] = *reinterpret_cast<const int*>(base);
                a[mt][1] = *reinterpret_cast<const int*>(base + 8 * KSTRIDE);
                a[mt][2] = *reinterpret_cast<const int*>(base + 16);
                a[mt][3] = *reinterpret_cast<const int*>(base + 8 * KSTRIDE + 16);
            }
            int b[8][2];
#pragma unroll
            for (int nt = 0; nt < 8; ++nt) {
                const int8_t* base = pB + (wn + nt * 8 + quad) * KSTRIDE + kk + four;
                b[nt][0] = *reinterpret_cast<const int*>(base);
                b[nt][1] = *reinterpret_cast<const int*>(base + 16);
            }
#pragma unroll
            for (int mt = 0; mt < 2; ++mt)
#pragma unroll
                for (int nt = 0; nt < 8; ++nt)
                    asm volatile(
                        "mma.sync.aligned.m16n8k32.row.col.s32.s8.s8.s32 "
                        "{%0,%1,%2,%3},{%4,%5,%6,%7},{%8,%9},{%0,%1,%2,%3};\n"
                        : "+r"(c[mt][nt][0]), "+r"(c[mt][nt][1]),
                          "+r"(c[mt][nt][2]), "+r"(c[mt][nt][3])
                        : "r"(a[mt][0]), "r"(a[mt][1]), "r"(a[mt][2]), "r"(a[mt][3]),
                          "r"(b[nt][0]), "r"(b[nt][1]));
        }
        __syncthreads();
    }

    // Epilogue: y = fp16(q * ws[n] * xs[m]); y += bias[n] in fp16 (as reference)
    bool f32io = (g_x_is_f32 != 0);
#pragma unroll
    for (int mt = 0; mt < 2; ++mt) {
        int r0 = m0 + wm + mt * 16 + quad;
        float xs0 = g_xs[r0], xs1 = g_xs[r0 + 8];
#pragma unroll
        for (int nt = 0; nt < 8; ++nt) {
            int cg = n0 + wn + nt * 8 + (lane & 3) * 2;
            float w0, w1;
            __half b0, b1;
            if (f32io) {
                w0 = ((const float*)wscv)[cg]; w1 = ((const float*)wscv)[cg + 1];
                b0 = __float2half(((const float*)biasv)[cg]);   // exact (orig fp16)
                b1 = __float2half(((const float*)biasv)[cg + 1]);
            } else {
                w0 = __half2float(((const __half*)wscv)[cg]);
                w1 = __half2float(((const __half*)wscv)[cg + 1]);
                b0 = ((const __half*)biasv)[cg];
                b1 = ((const __half*)biasv)[cg + 1];
            }
            __half y00 = __hadd(__float2half((float)c[mt][nt][0] * w0 * xs0), b0);
            __half y01 = __hadd(__float2half((float)c[mt][nt][1] * w1 * xs0), b1);
            __half y10 = __hadd(__float2half((float)c[mt][nt][2] * w0 * xs1), b0);
            __half y11 = __hadd(__float2half((float)c[mt][nt][3] * w1 * xs1), b1);
            if (f32io) {
                float* Y = (float*)Yv;
                if (r0 < T) *reinterpret_cast<float2*>(Y + (size_t)r0 * OUT_F + cg) =
                    make_float2(__half2float(y00), __half2float(y01));
                if (r0 + 8 < T) *reinterpret_cast<float2*>(Y + (size_t)(r0 + 8) * OUT_F + cg) =
                    make_float2(__half2float(y10), __half2float(y11));
            } else {
                __half* Y = (__half*)Yv;
                if (r0 < T) { __half2 o; o.x = y00; o.y = y01;
                    *reinterpret_cast<__half2*>(Y + (size_t)r0 * OUT_F + cg) = o; }
                if (r0 + 8 < T) { __half2 o; o.x = y10; o.y = y11;
                    *reinterpret_cast<__half2*>(Y + (size_t)(r0 + 8) * OUT_F + cg) = o; }
            }
        }
    }
}

// ---------------------------------------------------------------------------
extern "C" void kernel_launch(void* const* d_in, const int* in_sizes, int n_in,
                              void* d_out, int out_size) {
    const void* x    = d_in[0];
    const void* w    = d_in[1];
    const void* wsc  = d_in[2];
    const void* bias = d_in[3];
    int T = in_sizes[0] / IN_F;

    detect_kernel<<<1, 256>>>(x, w);
    repack_w_kernel<<<(OUT_F * IN_F / 4) / 256, 256>>>(w);
    quant_kernel<<<T, 256>>>(x, T);

    dim3 grid(OUT_F / BN, (T + BM - 1) / BM);
    gemm_kernel<<<grid, 256>>>(w, wsc, bias, d_out, T);
}

// round 8
// speedup vs baseline: 1.0868x; 1.0006x over previous
#include <cuda_runtime.h>
#include <cuda_fp16.h>
#include <cstdint>

#define IN_F 4096
#define OUT_F 4096
#define MAX_T 8192

#define BM 128
#define BN 128
#define BK 64
#define KSTRIDE (BK + 16)     // 80-byte smem row stride: conflict-free lane map
#define KT (IN_F / BK)        // 64 k-tiles
#define NST 3
#define A_STAGE (BM * KSTRIDE)                 // 10240 B
#define B_STAGE (BN * KSTRIDE)                 // 10240 B
#define GEMM_SMEM (NST * (A_STAGE + B_STAGE))  // 61440 B dynamic

#define REPACK_BLOCKS ((OUT_F * IN_F / 4) / 256)   // 16384

// Scratch (device globals: allocations are banned in kernel_launch)
__device__ __align__(16) int8_t g_qx[(size_t)MAX_T * IN_F];
__device__ __align__(16) int8_t g_qw[(size_t)OUT_F * IN_F];
__device__ float g_xs[MAX_T];
__device__ int g_x_is_f32;
__device__ int g_w_is_i32;

__device__ __forceinline__ void cp16(uint32_t dst, const void* src) {
    asm volatile("cp.async.cg.shared.global [%0], [%1], 16;\n" ::"r"(dst), "l"(src));
}
#define CP_COMMIT() asm volatile("cp.async.commit_group;\n")
#define CP_WAIT(n)  asm volatile("cp.async.wait_group %0;\n" ::"n"(n))

// ---------------------------------------------------------------------------
// Kernel 0: dtype detection, parallel (harness may promote fp16->fp32,
// int8->int32). Deterministic pure function of the inputs.
// ---------------------------------------------------------------------------
__global__ void detect_kernel(const void* xv, const void* wv) {
    __shared__ float sm[8];
    __shared__ int bad;
    int tid = threadIdx.x;
    if (tid == 0) bad = 0;
    __syncthreads();

    const float* xf = (const float*)xv;
    float m = 0.f;
#pragma unroll
    for (int i = 0; i < 16; i++) m = fmaxf(m, fabsf(xf[tid + 256 * i]));
#pragma unroll
    for (int o = 16; o > 0; o >>= 1) m = fmaxf(m, __shfl_xor_sync(~0u, m, o));
    int lane = tid & 31, wid = tid >> 5;
    if (lane == 0) sm[wid] = m;

    const int* wi = (const int*)wv;
    int v = wi[tid];
    if (v < -128 || v > 127) bad = 1;
    __syncthreads();

    if (tid == 0) {
        float mx = sm[0];
#pragma unroll
        for (int i = 1; i < 8; i++) mx = fmaxf(mx, sm[i]);
        g_x_is_f32 = (mx < 8.0f) ? 1 : 0;
        g_w_is_i32 = bad ? 0 : 1;
    }
}

// ---------------------------------------------------------------------------
// Kernel 1: FUSED weight repack (int32->int8) + per-token quantization.
// Blocks [0, REPACK_BLOCKS) repack; blocks [REPACK_BLOCKS, +T) quantize.
// Independent workloads -> one launch, concurrent execution.
// ---------------------------------------------------------------------------
__global__ void prep_kernel(const void* xv, const void* wv, int T) {
    if (blockIdx.x < REPACK_BLOCKS) {
        if (!g_w_is_i32) return;
        size_t idx = (size_t)blockIdx.x * blockDim.x + threadIdx.x;
        int4 v = ((const int4*)wv)[idx];
        char4 c;
        c.x = (char)v.x; c.y = (char)v.y; c.z = (char)v.z; c.w = (char)v.w;
        reinterpret_cast<char4*>(g_qw)[idx] = c;
        return;
    }
    int t = blockIdx.x - REPACK_BLOCKS;
    if (t >= T) return;
    int tid = threadIdx.x;
    float vals[16];
    if (g_x_is_f32) {
        const float4* row = reinterpret_cast<const float4*>((const float*)xv + (size_t)t * IN_F);
#pragma unroll
        for (int i = 0; i < 4; i++) {
            float4 v = row[tid * 4 + i];
            vals[4 * i] = v.x; vals[4 * i + 1] = v.y;
            vals[4 * i + 2] = v.z; vals[4 * i + 3] = v.w;
        }
    } else {
        const float4* row = reinterpret_cast<const float4*>((const __half*)xv + (size_t)t * IN_F);
        float4 v0 = row[tid * 2], v1 = row[tid * 2 + 1];
        const __half2* h0 = (const __half2*)&v0;
        const __half2* h1 = (const __half2*)&v1;
#pragma unroll
        for (int i = 0; i < 4; i++) {
            float2 f = __half22float2(h0[i]);
            vals[2 * i] = f.x; vals[2 * i + 1] = f.y;
        }
#pragma unroll
        for (int i = 0; i < 4; i++) {
            float2 f = __half22float2(h1[i]);
            vals[8 + 2 * i] = f.x; vals[8 + 2 * i + 1] = f.y;
        }
    }
    float m = 0.f;
#pragma unroll
    for (int i = 0; i < 16; i++) m = fmaxf(m, fabsf(vals[i]));
#pragma unroll
    for (int o = 16; o > 0; o >>= 1) m = fmaxf(m, __shfl_xor_sync(~0u, m, o));
    __shared__ float sm[8];
    int lane = tid & 31, wid = tid >> 5;
    if (lane == 0) sm[wid] = m;
    __syncthreads();
    if (tid < 8) {
        float v = sm[tid];
#pragma unroll
        for (int o = 4; o > 0; o >>= 1) v = fmaxf(v, __shfl_xor_sync(0xffu, v, o));
        if (tid == 0) sm[0] = v;
    }
    __syncthreads();
    float scale = sm[0] / 127.0f;
    if (tid == 0) g_xs[t] = scale;
    int8_t q[16];
#pragma unroll
    for (int i = 0; i < 16; i++) {
        float r = rintf(__fdiv_rn(vals[i], scale));
        r = fminf(fmaxf(r, -128.f), 127.f);
        q[i] = (int8_t)(int)r;
    }
    *reinterpret_cast<int4*>(g_qx + (size_t)t * IN_F + tid * 16) =
        *reinterpret_cast<const int4*>(q);
}

// ---------------------------------------------------------------------------
// Kernel 2: int8 GEMM — R7 compute body, 3-stage pipeline, ONE sync/iter.
// Invariant at head sync of iter kt: every thread has wait_group'ed stage kt
// (RAW), and all reads of stage (kt+2)%3 finished in iter kt-1 (WAR).
// Fragments via direct LDS.32 at PTX-spec lane coords (conflict-free,
// KSTRIDE=80). 8 warps: 4(M) x 2(N); warp tile 32x64; per-warp mma grid 2x8.
// ---------------------------------------------------------------------------
__global__ void __launch_bounds__(256, 2)
gemm_kernel(const void* Worig, const void* wscv, const void* biasv,
            void* Yv, int T) {
    extern __shared__ __align__(128) int8_t dsm[];

    int tid = threadIdx.x;
    int m0 = blockIdx.y * BM;
    int n0 = blockIdx.x * BN;
    const int8_t* W = g_w_is_i32 ? g_qw : (const int8_t*)Worig;

    // rotating stage pointers: cur (compute), nxt, fut (load target)
    int8_t* aCur = dsm;
    int8_t* aNxt = dsm + (A_STAGE + B_STAGE);
    int8_t* aFut = dsm + 2 * (A_STAGE + B_STAGE);
    // B lives at +A_STAGE within each stage block

    // per-thread loader coords (512 16B chunks per operand; 2 per thread)
    int lr0 = tid >> 2, lp0 = (tid & 3) * 16;          // chunk tid
    int lr1 = (tid + 256) >> 2, lp1 = lp0;             // chunk tid+256
    uint32_t so0 = lr0 * KSTRIDE + lp0;
    uint32_t so1 = lr1 * KSTRIDE + lp1;

    auto load_tile = [&](int8_t* stage, int k0) {
        uint32_t ab = (uint32_t)__cvta_generic_to_shared(stage);
        uint32_t bb = ab + A_STAGE;
        cp16(ab + so0, g_qx + (size_t)(m0 + lr0) * IN_F + k0 + lp0);
        cp16(ab + so1, g_qx + (size_t)(m0 + lr1) * IN_F + k0 + lp1);
        cp16(bb + so0, W + (size_t)(n0 + lr0) * IN_F + k0 + lp0);
        cp16(bb + so1, W + (size_t)(n0 + lr1) * IN_F + k0 + lp1);
    };

    int lane = tid & 31;
    int warp = tid >> 5;
    int wm = (warp & 3) * 32;
    int wn = (warp >> 2) * 64;
    int quad = lane >> 2;
    int four = (lane & 3) * 4;

    int c[2][8][4];
#pragma unroll
    for (int mt = 0; mt < 2; mt++)
#pragma unroll
        for (int nt = 0; nt < 8; nt++)
#pragma unroll
            for (int i = 0; i < 4; i++) c[mt][nt][i] = 0;

    load_tile(aCur, 0);
    CP_COMMIT();
    load_tile(aNxt, BK);
    CP_COMMIT();
    CP_WAIT(1);                 // stage 0 (this thread) complete

    for (int kt = 0; kt < KT; ++kt) {
        __syncthreads();        // RAW publish stage kt; WAR fence stage (kt+2)%3

        if (kt + 2 < KT) {
            load_tile(aFut, (kt + 2) * BK);
            CP_COMMIT();
        }

        const int8_t* pA = aCur;
        const int8_t* pB = aCur + A_STAGE;

#pragma unroll
        for (int kk = 0; kk < BK; kk += 32) {
            int a[2][4];
#pragma unroll
            for (int mt = 0; mt < 2; ++mt) {
                const int8_t* base = pA + (wm + mt * 16 + quad) * KSTRIDE + kk + four;
                a[mt][0] = *reinterpret_cast<const int*>(base);
                a[mt][1] = *reinterpret_cast<const int*>(base + 8 * KSTRIDE);
                a[mt][2] = *reinterpret_cast<const int*>(base + 16);
                a[mt][3] = *reinterpret_cast<const int*>(base + 8 * KSTRIDE + 16);
            }
            int b[8][2];
#pragma unroll
            for (int nt = 0; nt < 8; ++nt) {
                const int8_t* base = pB + (wn + nt * 8 + quad) * KSTRIDE + kk + four;
                b[nt][0] = *reinterpret_cast<const int*>(base);
                b[nt][1] = *reinterpret_cast<const int*>(base + 16);
            }
#pragma unroll
            for (int mt = 0; mt < 2; ++mt)
#pragma unroll
                for (int nt = 0; nt < 8; ++nt)
                    asm volatile(
                        "mma.sync.aligned.m16n8k32.row.col.s32.s8.s8.s32 "
                        "{%0,%1,%2,%3},{%4,%5,%6,%7},{%8,%9},{%0,%1,%2,%3};\n"
                        : "+r"(c[mt][nt][0]), "+r"(c[mt][nt][1]),
                          "+r"(c[mt][nt][2]), "+r"(c[mt][nt][3])
                        : "r"(a[mt][0]), "r"(a[mt][1]), "r"(a[mt][2]), "r"(a[mt][3]),
                          "r"(b[nt][0]), "r"(b[nt][1]));
        }

        // ensure group kt+1 complete (this thread) before next head sync
        if (kt + 2 < KT)      CP_WAIT(1);
        else if (kt + 1 < KT) CP_WAIT(0);

        int8_t* t0 = aCur; aCur = aNxt; aNxt = aFut; aFut = t0;
    }

    // Epilogue: y = fp16(q * ws[n] * xs[m]); y += bias[n] in fp16 (as reference)
    bool f32io = (g_x_is_f32 != 0);
#pragma unroll
    for (int mt = 0; mt < 2; ++mt) {
        int r0 = m0 + wm + mt * 16 + quad;
        float xs0 = g_xs[r0], xs1 = g_xs[r0 + 8];
#pragma unroll
        for (int nt = 0; nt < 8; ++nt) {
            int cg = n0 + wn + nt * 8 + (lane & 3) * 2;
            float w0, w1;
            __half b0, b1;
            if (f32io) {
                w0 = ((const float*)wscv)[cg]; w1 = ((const float*)wscv)[cg + 1];
                b0 = __float2half(((const float*)biasv)[cg]);   // exact (orig fp16)
                b1 = __float2half(((const float*)biasv)[cg + 1]);
            } else {
                w0 = __half2float(((const __half*)wscv)[cg]);
                w1 = __half2float(((const __half*)wscv)[cg + 1]);
                b0 = ((const __half*)biasv)[cg];
                b1 = ((const __half*)biasv)[cg + 1];
            }
            __half y00 = __hadd(__float2half((float)c[mt][nt][0] * w0 * xs0), b0);
            __half y01 = __hadd(__float2half((float)c[mt][nt][1] * w1 * xs0), b1);
            __half y10 = __hadd(__float2half((float)c[mt][nt][2] * w0 * xs1), b0);
            __half y11 = __hadd(__float2half((float)c[mt][nt][3] * w1 * xs1), b1);
            if (f32io) {
                float* Y = (float*)Yv;
                if (r0 < T) *reinterpret_cast<float2*>(Y + (size_t)r0 * OUT_F + cg) =
                    make_float2(__half2float(y00), __half2float(y01));
                if (r0 + 8 < T) *reinterpret_cast<float2*>(Y + (size_t)(r0 + 8) * OUT_F + cg) =
                    make_float2(__half2float(y10), __half2float(y11));
            } else {
                __half* Y = (__half*)Yv;
                if (r0 < T) { __half2 o; o.x = y00; o.y = y01;
                    *reinterpret_cast<__half2*>(Y + (size_t)r0 * OUT_F + cg) = o; }
                if (r0 + 8 < T) { __half2 o; o.x = y10; o.y = y11;
                    *reinterpret_cast<__half2*>(Y + (size_t)(r0 + 8) * OUT_F + cg) = o; }
            }
        }
    }
}

// ---------------------------------------------------------------------------
extern "C" void kernel_launch(void* const* d_in, const int* in_sizes, int n_in,
                              void* d_out, int out_size) {
    const void* x    = d_in[0];
    const void* w    = d_in[1];
    const void* wsc  = d_in[2];
    const void* bias = d_in[3];
    int T = in_sizes[0] / IN_F;

    cudaFuncSetAttribute(gemm_kernel,
        cudaFuncAttributeMaxDynamicSharedMemorySize, GEMM_SMEM);

    detect_kernel<<<1, 256>>>(x, w);
    prep_kernel<<<REPACK_BLOCKS + T, 256>>>(x, w, T);

    dim3 grid(OUT_F / BN, (T + BM - 1) / BM);
    gemm_kernel<<<grid, 256, GEMM_SMEM>>>(w, wsc, bias, d_out, T);
}